// round 17
// baseline (speedup 1.0000x reference)
#include <cuda_runtime.h>
#include <cuda_fp16.h>
#include <math.h>
#include <stdint.h>

// ---------------------------------------------------------------- constants
#define BROWS  131072
#define FEAT   64
#define HID    512
#define NB     10
#define PPF    29
#define PD     928
#define PDP    1024

#define BM      64             // rows per CTA (H tile lives in smem)
#define NT      128            // N per chunk (4 features x 32 padded params)
#define KT      32             // K per B stage
#define NCHUNKS (PDP/NT)       // 8
#define KSTAGES (HID/KT)       // 16
#define NBLKS   (BROWS/BM)     // 2048

// B stage tile: 128 N-rows x 40 halves (32 data + 8 pad, 80B rows)
#define BROWB   80
#define BT_BYTES (128*BROWB)       // 10240
// H smem: 64 rows x 520 halves (512 data + 8 pad) -> conflict-free ldmatrix
#define HROWW  520
#define SM_H   0
#define SM_B   (64*HROWW*2)        // 66560
#define SM_CS  (SM_B + 2*BT_BYTES) // 87040
#define CSTRIDE 134                // halves; 67 words odd -> spline conflict-free
#define SM_RED (SM_CS + BM*CSTRIDE*2)  // 104192 (lad[64] + ot[64])
#define SM_MBAR (SM_RED + 512)         // 104704
#define SMEM_TOTAL (SM_MBAR + 16)      // 104720 -> 2 CTAs/SM

// ---------------------------------------------------------------- asm helpers
__device__ __forceinline__ uint32_t smem_u32(const void* p) {
    uint32_t a;
    asm("{ .reg .u64 t; cvta.to.shared.u64 t, %1; cvt.u32.u64 %0, t; }" : "=r"(a) : "l"(p));
    return a;
}
#define MBARRIER_INIT(addr, cnt) \
    asm volatile("mbarrier.init.shared.b64 [%0], %1;" :: "r"(addr), "r"(cnt) : "memory")
#define MBARRIER_EXPECT_TX(addr, bytes) \
    asm volatile("mbarrier.arrive.expect_tx.shared.b64 _, [%0], %1;" :: "r"(addr), "r"(bytes) : "memory")
#define MBARRIER_WAIT_PARITY(addr, par) do { \
    uint32_t _m = (addr), _p = (par), _d; \
    asm volatile("{ .reg .pred p; mbarrier.try_wait.parity.acquire.cta.shared::cta.b64 p, [%1], %2; selp.b32 %0,1,0,p; }" \
        : "=r"(_d) : "r"(_m), "r"(_p) : "memory"); \
    if (!_d) { \
        asm volatile("{ .reg .pred P1;\nWL_%=:\nmbarrier.try_wait.parity.acquire.cta.shared::cta.b64 P1, [%0], %1, 0x989680;\n@P1 bra.uni WD_%=;\nbra.uni WL_%=;\nWD_%=:\n}" \
            :: "r"(_m), "r"(_p) : "memory"); \
    } } while (0)
#define BULK_LD(dst, src, sz, mb) \
    asm volatile("cp.async.bulk.shared::cluster.global.mbarrier::complete_tx::bytes [%0], [%1], %2, [%3];" \
        :: "r"(dst), "l"(src), "r"(sz), "r"(mb) : "memory")

#define LDSM_X4(r, addr) \
    asm volatile("ldmatrix.sync.aligned.m8n8.x4.shared.b16 {%0,%1,%2,%3}, [%4];" \
        : "=r"((r)[0]), "=r"((r)[1]), "=r"((r)[2]), "=r"((r)[3]) : "r"(addr))

#define MMA16816(d, a, b) \
    asm volatile("mma.sync.aligned.m16n8k16.row.col.f32.f16.f16.f32 " \
        "{%0,%1,%2,%3},{%4,%5,%6,%7},{%8,%9},{%0,%1,%2,%3};" \
        : "+f"((d)[0]), "+f"((d)[1]), "+f"((d)[2]), "+f"((d)[3]) \
        : "r"((a)[0]), "r"((a)[1]), "r"((a)[2]), "r"((a)[3]), "r"((b)[0]), "r"((b)[1]))

// ---------------------------------------------------------------- scratch
__device__ __half g_W2t[NCHUNKS * KSTAGES * 128 * 40];   // stage-tiled W2^T, 1.3 MB
__device__ __half g_W1t[4 * 128 * 40];                   // stage-tiled W1^T, 40 KB
__device__ float  g_b2p[PDP];

// ---------------------------------------------------------------- prep
__global__ void prep_kernel(const float* __restrict__ W2, const float* __restrict__ b2,
                            const float* __restrict__ W1) {
    int idx = blockIdx.x * blockDim.x + threadIdx.x;
    if (idx < PDP * HID) {
        int n = idx >> 9;        // padded param col 0..1023
        int k = idx & 511;
        int f = n >> 5, p = n & 31;
        float w = (p < PPF) ? W2[k * PD + f * PPF + p] : 0.0f;
        size_t a = ((size_t)((n >> 7) * KSTAGES + (k >> 5)) * 128 + (n & 127)) * 40 + (k & 31);
        g_W2t[a] = __float2half_rn(w);
    }
    if (idx < HID * 32) {
        int n = idx >> 5, k = idx & 31;   // W1[k][n] -> tile (n>>7), row n&127, col k
        g_W1t[((n >> 7) * 128 + (n & 127)) * 40 + k] = __float2half_rn(W1[k * HID + n]);
    }
    if (idx < PDP) {
        int f = idx >> 5, p = idx & 31;
        g_b2p[idx] = (p < PPF) ? b2[f * PPF + p] : 0.0f;
    }
}

// ---------------------------------------------------------------- spline
__device__ __forceinline__ float expp(float x) {
    float r = 8.333333333e-3f;
    r = r * x + 4.166666667e-2f;
    r = r * x + 1.666666667e-1f;
    r = r * x + 0.5f;
    r = r * x + 1.0f;
    r = r * x + 1.0f;
    return r;
}
__device__ __forceinline__ float softplusf_fast(float v) {
    return fmaxf(v, 0.0f) + __logf(1.0f + __expf(-fabsf(v)));
}

__device__ __forceinline__ void rqs_spline(float xv, const __half* __restrict__ p,
                                           float& y_out, float& lad_out)
{
    const float S = 0.044194173824159216f;  // 1/sqrt(512)
    bool inside = (xv >= -1.0f) && (xv <= 1.0f);
    float xc = fminf(fmaxf(xv, -1.0f), 1.0f);

    float vw[10], vh[10];
    float sw = 0.0f, sh = 0.0f;
#pragma unroll
    for (int i = 0; i < 10; i++) {
        vw[i] = expp(__half2float(p[i]) * S);
        vh[i] = expp(__half2float(p[10 + i]) * S);
        sw += vw[i];
        sh += vh[i];
    }
    float rw = __fdividef(0.99f, sw), rh = __fdividef(0.99f, sh);

    float cumw = 0.0f, cumh = 0.0f;
    float Lw = -1.0f, Lh = -1.0f;
    float icw = -1.0f, iw = 1.0f, ich = -1.0f, ih = 1.0f;
    int isel = 0;
#pragma unroll
    for (int i = 0; i < 10; i++) {
        cumw += 0.001f + vw[i] * rw;
        cumh += 0.001f + vh[i] * rh;
        float Rw = (i == 9) ? 1.0f : (2.0f * cumw - 1.0f);
        float Rh = (i == 9) ? 1.0f : (2.0f * cumh - 1.0f);
        if (xc >= Lw) {
            icw = Lw; iw = Rw - Lw;
            ich = Lh; ih = Rh - Lh;
            isel = i;
        }
        Lw = Rw; Lh = Rh;
    }
    float dk  = (isel > 0) ? (0.001f + softplusf_fast(__half2float(p[19 + isel]))) : 1.0f;
    float dk1 = (isel < 9) ? (0.001f + softplusf_fast(__half2float(p[20 + isel]))) : 1.0f;

    float riw = __fdividef(1.0f, iw);
    float theta = (xc - icw) * riw;
    float om = 1.0f - theta;
    float t1m = theta * om;
    float delta = ih * riw;
    float numer = ih * (delta * theta * theta + dk * t1m);
    float denom = delta + (dk + dk1 - 2.0f * delta) * t1m;
    float rden = __fdividef(1.0f, denom);
    float yv = ich + numer * rden;
    float dnum = delta * delta * (dk1 * theta * theta + 2.0f * delta * t1m + dk * om * om);
    float l = __logf(dnum * rden * rden);

    y_out = inside ? yv : xv;
    lad_out = inside ? l : 0.0f;
}

// ---------------------------------------------------------------- fused kernel
__global__ __launch_bounds__(256, 2) void fused_kernel(
    const float* __restrict__ x, const float* __restrict__ b1,
    float* __restrict__ out, float* __restrict__ lad_out, float* __restrict__ ot_out)
{
    extern __shared__ char smem[];
    uint32_t sb = smem_u32(smem);
    int tid = threadIdx.x;
    int wid = tid >> 5, lane = tid & 31;
    size_t rb = (size_t)blockIdx.x * BM;

    int warpRow = (wid & 3) * 16;        // 4 warp-rows of 16 (mt=1)
    int warpCol = (wid >> 2) * 64;       // 2 warp-cols of 64 (8 n8)

    __half*  CsH  = (__half*)(smem + SM_CS);
    __half2* CsH2 = (__half2*)(smem + SM_CS);
    float* ladR = (float*)(smem + SM_RED);
    float* otR  = (float*)(smem + SM_RED + 256);

    int aRow = (lane & 15);
    int aKof = (lane >> 4) * 8;
    int bN   = (lane & 7) + ((lane >> 4) << 3);
    int bKof = ((lane >> 3) & 1) * 8;

    float lad_acc = 0.0f, ot_acc = 0.0f;

    if (tid == 0) {
        MBARRIER_INIT(sb + SM_MBAR, 1);
        MBARRIER_INIT(sb + SM_MBAR + 8, 1);
    }
    if (tid < 64) { ladR[tid] = 0.0f; otR[tid] = 0.0f; }
    __syncthreads();

    // ---- load x identity cols into Xa (aliases Cs region; 64x40 halves) ----
    char* Xa = smem + SM_CS;
#pragma unroll
    for (int j = 0; j < 4; j++) {
        int idx = tid + 256 * j;          // 0..1023
        int row = idx >> 4, c = idx & 15;
        float4 v = __ldg((const float4*)x + (rb + row) * 16 + c);
        *(__half2*)(Xa + row * BROWB + c * 4) = __floats2half2_rn(v.y, v.w);
    }
    // prefetch W1 tiles 0,1
    if (tid == 0) {
        MBARRIER_EXPECT_TX(sb + SM_MBAR, BT_BYTES);
        BULK_LD(sb + SM_B, (const char*)g_W1t, BT_BYTES, sb + SM_MBAR);
        MBARRIER_EXPECT_TX(sb + SM_MBAR + 8, BT_BYTES);
        BULK_LD(sb + SM_B + BT_BYTES, (const char*)g_W1t + BT_BYTES, BT_BYTES, sb + SM_MBAR + 8);
    }
    __syncthreads();   // Xa visible to all warps
    int ph0 = 0, ph1 = 0;

    // ================= fused gemm1: H = relu(Xa @ W1) -> smem H =================
#pragma unroll 1
    for (int ch = 0; ch < 4; ch++) {
        int buf = ch & 1;
        if (buf == 0) { MBARRIER_WAIT_PARITY(sb + SM_MBAR,     ph0); ph0 ^= 1; }
        else          { MBARRIER_WAIT_PARITY(sb + SM_MBAR + 8, ph1); ph1 ^= 1; }
        __syncthreads();
        // issue stage ch+1 into buf^1 ONLY from ch>=1 (stages 0,1 were prefetched;
        // the missing ch>=1 guard in R16 double-issued stage 1 -> mbarrier UB)
        if (tid == 0 && ch >= 1 && ch + 1 < 4) {
            uint32_t mb = sb + SM_MBAR + ((ch + 1) & 1) * 8;
            MBARRIER_EXPECT_TX(mb, BT_BYTES);
            BULK_LD(sb + SM_B + ((ch + 1) & 1) * BT_BYTES,
                    (const char*)g_W1t + (size_t)(ch + 1) * BT_BYTES, BT_BYTES, mb);
        }

        float acc[8][4];
#pragma unroll
        for (int nt = 0; nt < 8; nt++)
#pragma unroll
            for (int r = 0; r < 4; r++) acc[nt][r] = 0.0f;

        uint32_t bbase = sb + SM_B + buf * BT_BYTES;
#pragma unroll
        for (int k16 = 0; k16 < 2; k16++) {
            uint32_t ah[4];
            LDSM_X4(ah, sb + SM_CS + (uint32_t)((warpRow + aRow) * BROWB + (k16 * 16 + aKof) * 2));
#pragma unroll
            for (int p = 0; p < 4; p++) {
                uint32_t bh[4];
                LDSM_X4(bh, bbase + (uint32_t)((warpCol + p * 16 + bN) * BROWB + (k16 * 16 + bKof) * 2));
                MMA16816(acc[2 * p],     ah, bh);
                MMA16816(acc[2 * p + 1], ah, bh + 2);
            }
        }

        // epilogue: bias + relu -> H smem
#pragma unroll
        for (int nt = 0; nt < 8; nt++) {
            int r = warpRow + (lane >> 2);
            int c = ch * 128 + warpCol + nt * 8 + (lane & 3) * 2;
            float2 bb = __ldg((const float2*)(b1 + c));
            ((__half2*)(smem + SM_H))[(r * HROWW + c) >> 1] =
                __floats2half2_rn(fmaxf(acc[nt][0] + bb.x, 0.f), fmaxf(acc[nt][1] + bb.y, 0.f));
            ((__half2*)(smem + SM_H))[((r + 8) * HROWW + c) >> 1] =
                __floats2half2_rn(fmaxf(acc[nt][2] + bb.x, 0.f), fmaxf(acc[nt][3] + bb.y, 0.f));
        }
    }
    __syncthreads();   // H complete + both B bufs free

    // prefetch gemm2 chunk0 stages 0,1
    if (tid == 0) {
        MBARRIER_EXPECT_TX(sb + SM_MBAR, BT_BYTES);
        BULK_LD(sb + SM_B, (const char*)g_W2t, BT_BYTES, sb + SM_MBAR);
        MBARRIER_EXPECT_TX(sb + SM_MBAR + 8, BT_BYTES);
        BULK_LD(sb + SM_B + BT_BYTES, (const char*)g_W2t + BT_BYTES, BT_BYTES, sb + SM_MBAR + 8);
    }

    // ================= gemm2: params chunks + spline =================
#pragma unroll 1
    for (int nc = 0; nc < NCHUNKS; nc++) {
        float acc[8][4];
#pragma unroll
        for (int nt = 0; nt < 8; nt++)
#pragma unroll
            for (int r = 0; r < 4; r++) acc[nt][r] = 0.0f;

#pragma unroll 1
        for (int kt = 0; kt < KSTAGES; kt++) {
            int buf = kt & 1;
            if (buf == 0) { MBARRIER_WAIT_PARITY(sb + SM_MBAR,     ph0); ph0 ^= 1; }
            else          { MBARRIER_WAIT_PARITY(sb + SM_MBAR + 8, ph1); ph1 ^= 1; }
            __syncthreads();
            if (tid == 0 && kt >= 1 && kt < KSTAGES - 1) {
                uint32_t mb = sb + SM_MBAR + ((kt + 1) & 1) * 8;
                MBARRIER_EXPECT_TX(mb, BT_BYTES);
                BULK_LD(sb + SM_B + ((kt + 1) & 1) * BT_BYTES,
                        (const char*)g_W2t + (size_t)(nc * KSTAGES + kt + 1) * BT_BYTES,
                        BT_BYTES, mb);
            }

            uint32_t bbase = sb + SM_B + buf * BT_BYTES;
#pragma unroll
            for (int k16 = 0; k16 < 2; k16++) {
                int kg = kt * KT + k16 * 16;
                uint32_t ah[4];
                LDSM_X4(ah, sb + SM_H + (uint32_t)((warpRow + aRow) * HROWW * 2 + (kg + aKof) * 2));
#pragma unroll
                for (int p = 0; p < 4; p++) {
                    uint32_t bh[4];
                    LDSM_X4(bh, bbase + (uint32_t)((warpCol + p * 16 + bN) * BROWB + (k16 * 16 + bKof) * 2));
                    MMA16816(acc[2 * p],     ah, bh);
                    MMA16816(acc[2 * p + 1], ah, bh + 2);
                }
            }
        }
        __syncthreads();   // both bufs consumed

        // prefetch both stages of next chunk; they fly under dump+spline
        if (tid == 0 && nc + 1 < NCHUNKS) {
            MBARRIER_EXPECT_TX(sb + SM_MBAR, BT_BYTES);
            BULK_LD(sb + SM_B, (const char*)g_W2t + (size_t)(nc + 1) * KSTAGES * BT_BYTES,
                    BT_BYTES, sb + SM_MBAR);
            MBARRIER_EXPECT_TX(sb + SM_MBAR + 8, BT_BYTES);
            BULK_LD(sb + SM_B + BT_BYTES,
                    (const char*)g_W2t + ((size_t)(nc + 1) * KSTAGES + 1) * BT_BYTES,
                    BT_BYTES, sb + SM_MBAR + 8);
        }

        // ---- dump accumulators (+ bias) into fp16 Cs ----
#pragma unroll
        for (int nt = 0; nt < 8; nt++) {
            int c = warpCol + nt * 8 + (lane & 3) * 2;
            float2 bb = __ldg((const float2*)(g_b2p + nc * NT + c));
            int r = warpRow + (lane >> 2);
            CsH2[(r * CSTRIDE + c) >> 1] =
                __floats2half2_rn(acc[nt][0] + bb.x, acc[nt][1] + bb.y);
            CsH2[((r + 8) * CSTRIDE + c) >> 1] =
                __floats2half2_rn(acc[nt][2] + bb.x, acc[nt][3] + bb.y);
        }
        __syncthreads();

        // ---- spline: 64 rows x 4 features = 256 tasks, 1/thread ----
        {
            int row = tid & 63;
            int fl  = tid >> 6;
            int fg  = nc * 4 + fl;
            const __half* bp = CsH + row * CSTRIDE + fl * 32;
            float2 xp = *(const float2*)(x + (rb + row) * FEAT + 2 * fg);
            float y, lad;
            rqs_spline(xp.x, bp, y, lad);
            *(float2*)(out + (rb + row) * FEAT + 2 * fg) = make_float2(y, xp.y);
            lad_acc += lad;
            float d = xp.x - y;
            ot_acc += d * d;
        }
        // next chunk's kt=0 sync orders spline reads before the next dump
    }

    // ---- final reduction: 4 threads per row via smem atomics ----
    __syncthreads();
    atomicAdd(&ladR[tid & 63], lad_acc);
    atomicAdd(&otR[tid & 63],  ot_acc);
    __syncthreads();
    if (tid < 64) {
        lad_out[rb + tid] = ladR[tid];
        ot_out[rb + tid]  = otR[tid];
    }
}

// ---------------------------------------------------------------- launcher
extern "C" void kernel_launch(void* const* d_in, const int* in_sizes, int n_in,
                              void* d_out, int out_size)
{
    const float* x  = (const float*)d_in[0];
    const float* W1 = (const float*)d_in[1];
    const float* b1 = (const float*)d_in[2];
    const float* W2 = (const float*)d_in[3];
    const float* b2 = (const float*)d_in[4];

    float* out = (float*)d_out;
    float* lad = out + (size_t)BROWS * FEAT;
    float* ot  = lad + BROWS;

    cudaFuncSetAttribute(fused_kernel, cudaFuncAttributeMaxDynamicSharedMemorySize, SMEM_TOTAL);

    prep_kernel<<<(PDP * HID + 255) / 256, 256>>>(W2, b2, W1);
    fused_kernel<<<NBLKS, 256, SMEM_TOTAL>>>(x, b1, out, lad, ot);
}